// round 12
// baseline (speedup 1.0000x reference)
#include <cuda_runtime.h>
#include <cuda_bf16.h>
#include <math.h>

// Fixed shapes: cls_conv_out (4, 1029, 100, 100) fp32; rois (2000,4) int32.
// Only batch 3 used. Output (2000, 21, 1, 1) fp32.
#define KK       7
#define C1       21
#define NJL      49
#define H        100
#define W        100
#define HP       101
#define ROW_S    2124                 // HP*C1=2121 padded to mult of 4 (16B rows)
#define PLANE_S  (HP * ROW_S)
#define IN_BASE  (3 * 1029 * 10000)   // batch 3 offset
#define NS       10                   // strips over y
#define RPS      10                   // rows per strip
#define NBUF     4                    // smem row ring

// Strip-LOCAL integrals (rows 1..100; row y is local to strip (y-1)/10).
__device__ float g_integral[(size_t)NJL * PLANE_S];
// Per-strip base offsets: g_off[jl][s][x*21+c] = global integral at y = s*10.
__device__ float g_off[(size_t)NJL * NS * ROW_S];

// ---------------------------------------------------------------------------
// Fused x-scan + strip-local y-cumsum. Block = (strip, jl); 21 warps = one
// channel each. Per row: one 25-lane shuffle scan, y-accumulate in per-lane
// float4 registers, conflict-free scatter-STS into a transposed row buffer,
// cp.async.bulk row store (4-deep ring). Strip total == last local row.
// ---------------------------------------------------------------------------
__global__ void __launch_bounds__(672) fused_scan(const float* __restrict__ in) {
    const int s    = blockIdx.x;       // 0..9
    const int jl   = blockIdx.y;       // 0..48
    const int t    = threadIdx.x;
    const int c    = t >> 5;           // warp id == channel 0..20
    const int lane = t & 31;

    __shared__ __align__(16) float smt[NBUF][ROW_S];  // transposed row bufs

    // zero x=0 column (21) + tail padding (3) of every buffer, once;
    // STS below never touches these slots, so zeros persist across reuse.
    if (t < 24) {
        const int idx = (t < C1) ? t : (2121 + t - C1);
        #pragma unroll
        for (int b = 0; b < NBUF; b++) smt[b][idx] = 0.0f;
    }

    const float4* src4 = (const float4*)(in + IN_BASE
                        + (size_t)jl * (C1 * H * W) + (size_t)c * (H * W));
    float* gplane = g_integral + (size_t)jl * PLANE_S;

    float4 acc  = make_float4(0.f, 0.f, 0.f, 0.f);
    float4 vcur = make_float4(0.f, 0.f, 0.f, 0.f);
    if (lane < 25) vcur = src4[(s * RPS) * (W / 4) + lane];

    for (int r = 0; r < RPS; r++) {
        float4 vnext = make_float4(0.f, 0.f, 0.f, 0.f);
        if (r < RPS - 1 && lane < 25)
            vnext = src4[(s * RPS + r + 1) * (W / 4) + lane];

        // x-scan of vcur: in-thread scan of 4 + shfl_up over lanes
        float s0 = vcur.x;
        float s1 = s0 + vcur.y;
        float s2 = s1 + vcur.z;
        float s3 = s2 + vcur.w;
        float run = s3;
        #pragma unroll
        for (int d = 1; d < 32; d <<= 1) {
            float u = __shfl_up_sync(0xffffffffu, run, d);
            if (lane >= d) run += u;
        }
        const float off = run - s3;

        // y-accumulate (strip-local integral) in registers
        acc.x += off + s0;
        acc.y += off + s1;
        acc.z += off + s2;
        acc.w += off + s3;

        // scatter-STS into transposed buffer: out position x+1 for x=4l+i.
        // bank = (84l + 21i + 21 + c)/4 mod 32 -> 21l mod 32, conflict-free.
        float* buf = smt[r & (NBUF - 1)];
        if (lane < 25) {
            float* sl = buf + 84 * lane + C1 + c;
            sl[0]      = acc.x;
            sl[C1]     = acc.y;
            sl[2 * C1] = acc.z;
            sl[3 * C1] = acc.w;
        }
        __syncthreads();                       // STS of row r complete

        if (t == 0) {
            asm volatile("fence.proxy.async.shared::cta;" ::: "memory");
            unsigned sa;
            asm("{ .reg .u64 a; cvta.to.shared.u64 a, %1; cvt.u32.u64 %0, a; }"
                : "=r"(sa) : "l"(buf));
            float* gd = gplane + (size_t)(s * RPS + r + 1) * ROW_S;
            asm volatile(
                "cp.async.bulk.global.shared::cta.bulk_group [%0], [%1], %2;"
                :: "l"(gd), "r"(sa), "r"(ROW_S * 4) : "memory");
            asm volatile("cp.async.bulk.commit_group;" ::: "memory");
            asm volatile("cp.async.bulk.wait_group 3;" ::: "memory");
        }
        __syncthreads();                       // ring slot r-3 reusable

        vcur = vnext;
    }

    if (t == 0)
        asm volatile("cp.async.bulk.wait_group 0;" ::: "memory");
}

// ---------------------------------------------------------------------------
// Fixup: per (jl, slot4): exclusive prefix over strip totals, where the strip
// total of s' is the local row y=(s'+1)*10.  off[s] = global I at y = s*10.
// ---------------------------------------------------------------------------
__global__ void fixup() {
    const int jl    = blockIdx.y;
    const int slot4 = blockIdx.x * blockDim.x + threadIdx.x;
    if (slot4 >= ROW_S / 4) return;

    const float4* L = (const float4*)(g_integral + (size_t)jl * PLANE_S) + slot4;
    float4*       O = (float4*)(g_off + (size_t)jl * NS * ROW_S) + slot4;

    float4 run = make_float4(0.f, 0.f, 0.f, 0.f);
    #pragma unroll
    for (int s = 0; s < NS; s++) {
        O[(size_t)s * (ROW_S / 4)] = run;
        float4 v = L[(size_t)(s + 1) * RPS * (ROW_S / 4)];
        run.x += v.x; run.y += v.y; run.z += v.z; run.w += v.w;
    }
}

// ---------------------------------------------------------------------------
// Kernel C: one block per ROI. Corner value = local[y] + off[(y-1)/10]
// (0 if y==0). Register pre-reduction, 21-thread final sum, warp softmax.
// ---------------------------------------------------------------------------
__global__ void pool_softmax(const int* __restrict__ rois,
                             float* __restrict__ out) {
    const int roi = blockIdx.x;
    const int t   = threadIdx.x;
    __shared__ float s_part[336];
    __shared__ float s_avg[C1];

    const int4 r = ((const int4*)rois)[roi];   // ymin, xmin, ymax, xmax
    const int ys = (r.z - r.x) / KK;
    const int xs = (r.w - r.y) / KK;

    if (t < 336) {
        const int c   = t % C1;
        const int jl0 = t / C1;   // 0..15
        float part = 0.0f;
        #pragma unroll
        for (int jl = jl0; jl < NJL; jl += 16) {
            const int j = jl / KK, l = jl - j * KK;
            const int y0 = r.x + j * ys, y1 = y0 + ys;
            const int x0 = r.y + l * xs, x1 = x0 + xs;
            const float* P = g_integral + (size_t)jl * PLANE_S;
            const float* O = g_off + (size_t)jl * NS * ROW_S;
            const int st1 = (y1 - 1) / NS;
            const float a = P[(size_t)y1 * ROW_S + x1 * C1 + c]
                          + O[(size_t)st1 * ROW_S + x1 * C1 + c];
            const float d = P[(size_t)y1 * ROW_S + x0 * C1 + c]
                          + O[(size_t)st1 * ROW_S + x0 * C1 + c];
            float b = 0.f, e = 0.f;
            if (y0 > 0) {
                const int st0 = (y0 - 1) / NS;
                b = P[(size_t)y0 * ROW_S + x1 * C1 + c]
                  + O[(size_t)st0 * ROW_S + x1 * C1 + c];
                e = P[(size_t)y0 * ROW_S + x0 * C1 + c]
                  + O[(size_t)st0 * ROW_S + x0 * C1 + c];
            }
            part += (a - b) - (d - e);
        }
        s_part[t] = part;
    }
    __syncthreads();

    if (t < C1) {
        float acc = 0.0f;
        #pragma unroll
        for (int g = 0; g < 16; g++) acc += s_part[g * C1 + t];
        s_avg[t] = acc / (49.0f * (float)(ys * xs));
    }
    __syncthreads();

    if (t < 32) {
        const bool act = t < C1;
        float v = act ? s_avg[t] : -INFINITY;
        float m = v;
        #pragma unroll
        for (int o = 16; o; o >>= 1) m = fmaxf(m, __shfl_xor_sync(0xffffffffu, m, o));
        float e = act ? expf(v - m) : 0.0f;
        float sum = e;
        #pragma unroll
        for (int o = 16; o; o >>= 1) sum += __shfl_xor_sync(0xffffffffu, sum, o);
        if (act) out[(size_t)roi * C1 + t] = e / sum;
    }
}

// ---------------------------------------------------------------------------
extern "C" void kernel_launch(void* const* d_in, const int* in_sizes, int n_in,
                              void* d_out, int out_size) {
    const float* x    = (const float*)d_in[0];
    const int*   rois = (const int*)d_in[1];
    float*       out  = (float*)d_out;
    const int n_rois  = in_sizes[1] / 4;   // 2000

    dim3 gF(NS, NJL);                      // 10 x 49 = 490 blocks, 672 thr
    fused_scan<<<gF, 672>>>(x);

    dim3 gX((ROW_S / 4 + 127) / 128, NJL); // 5 x 49
    fixup<<<gX, 128>>>();

    pool_softmax<<<n_rois, 352>>>(rois, out);
}